// round 4
// baseline (speedup 1.0000x reference)
#include <cuda_runtime.h>
#include <cuda_bf16.h>
#include <cstddef>

// Problem constants
#define BB 2
#define TT 2048
#define CC 1024
#define NHH 16
#define HDD 64
#define FFF 4096
#define MM (BB*TT)   // 4096

// ---------------------------------------------------------------------------
// Scratch (static device arrays — allocation-free per harness rules)
// ---------------------------------------------------------------------------
__device__ float g_h [MM*CC];   // LN1 output
__device__ float g_q [MM*CC];
__device__ float g_k [MM*CC];
__device__ float g_v [MM*CC];
__device__ float g_o [MM*CC];   // attention output, [B,T,C] layout
__device__ float g_x1[MM*CC];   // x + attn proj (residual 1)
__device__ float g_h2[MM*CC];   // LN2 output
__device__ float g_ff[MM*FFF];  // relu(h2@W1+b1)

// ---------------------------------------------------------------------------
// LayerNorm: one block per row, 256 threads, C=1024 (4 floats / thread)
// ---------------------------------------------------------------------------
__global__ __launch_bounds__(256) void ln_kernel(
    const float* __restrict__ x, const float* __restrict__ w,
    const float* __restrict__ bb, float* __restrict__ out)
{
    const int row = blockIdx.x;
    const int tid = threadIdx.x;
    const float* xr = x + (size_t)row * CC;
    float4 xv = ((const float4*)xr)[tid];

    float s  = xv.x + xv.y + xv.z + xv.w;
    float sq = xv.x*xv.x + xv.y*xv.y + xv.z*xv.z + xv.w*xv.w;

    #pragma unroll
    for (int m = 16; m > 0; m >>= 1) {
        s  += __shfl_xor_sync(0xffffffffu, s,  m);
        sq += __shfl_xor_sync(0xffffffffu, sq, m);
    }
    __shared__ float ss[8], ssq[8];
    const int lane = tid & 31, wid = tid >> 5;
    if (lane == 0) { ss[wid] = s; ssq[wid] = sq; }
    __syncthreads();
    float ts = 0.f, tsq = 0.f;
    #pragma unroll
    for (int i = 0; i < 8; i++) { ts += ss[i]; tsq += ssq[i]; }

    const float mu  = ts * (1.0f / CC);
    const float var = tsq * (1.0f / CC) - mu * mu;
    const float rs  = rsqrtf(var + 1e-5f);

    float4 wv = ((const float4*)w)[tid];
    float4 bv = ((const float4*)bb)[tid];
    float4 ov;
    ov.x = (xv.x - mu) * rs * wv.x + bv.x;
    ov.y = (xv.y - mu) * rs * wv.y + bv.y;
    ov.z = (xv.z - mu) * rs * wv.z + bv.z;
    ov.w = (xv.w - mu) * rs * wv.w + bv.w;
    ((float4*)(out + (size_t)row * CC))[tid] = ov;
}

// ---------------------------------------------------------------------------
// SGEMM: C[M,N] = A[M,K] @ B[K,N] (+bias[N]) (+resid[M,N]) (relu?)
// 128x128 block tile, BK=16, 8x8 per thread, 256 threads.
// M,N multiples of 128; K multiple of 16 (true for all 6 GEMMs here).
// ---------------------------------------------------------------------------
__global__ __launch_bounds__(256) void sgemm_kernel(
    const float* __restrict__ A, const float* __restrict__ B,
    const float* __restrict__ bias, const float* __restrict__ resid,
    float* __restrict__ Cmat, int M, int N, int K, int do_relu)
{
    __shared__ float As[16][132];   // transposed, padded; rows 16B-aligned (132 % 4 == 0)
    __shared__ float Bs[16][128];

    const int tid = threadIdx.x;
    const int tx = tid & 15;        // 16 col-groups of 8
    const int ty = tid >> 4;        // 16 row-groups of 8
    const int bm = blockIdx.y, bn = blockIdx.x;

    const float* Ab = A + (size_t)bm * 128 * K;
    const float* Bb = B + (size_t)bn * 128;

    float acc[8][8];
    #pragma unroll
    for (int i = 0; i < 8; i++)
        #pragma unroll
        for (int j = 0; j < 8; j++) acc[i][j] = 0.f;

    for (int k0 = 0; k0 < K; k0 += 16) {
        // load A tile (128x16), store transposed (scalar STS — transposed)
        #pragma unroll
        for (int s = 0; s < 2; s++) {
            int idx = tid + s * 256;           // 0..511
            int r   = idx >> 2;                // 0..127
            int c4  = (idx & 3) << 2;          // 0,4,8,12
            float4 a = *(const float4*)(Ab + (size_t)r * K + k0 + c4);
            As[c4 + 0][r] = a.x; As[c4 + 1][r] = a.y;
            As[c4 + 2][r] = a.z; As[c4 + 3][r] = a.w;
        }
        // load B tile (16x128)
        #pragma unroll
        for (int s = 0; s < 2; s++) {
            int idx = tid + s * 256;
            int r   = idx >> 5;                // 0..15
            int cc  = (idx & 31) << 2;         // 0..124
            *(float4*)(&Bs[r][cc]) = *(const float4*)(Bb + (size_t)(k0 + r) * N + cc);
        }
        __syncthreads();

        #pragma unroll
        for (int kk = 0; kk < 16; kk++) {
            float ar[8], br[8];
            float4 a0 = *(float4*)(&As[kk][ty * 8]);      // aligned: 132%4==0, ty*8%4==0
            float4 a1 = *(float4*)(&As[kk][ty * 8 + 4]);
            ar[0] = a0.x; ar[1] = a0.y; ar[2] = a0.z; ar[3] = a0.w;
            ar[4] = a1.x; ar[5] = a1.y; ar[6] = a1.z; ar[7] = a1.w;
            float4 b0 = *(float4*)(&Bs[kk][tx * 8]);
            float4 b1 = *(float4*)(&Bs[kk][tx * 8 + 4]);
            br[0] = b0.x; br[1] = b0.y; br[2] = b0.z; br[3] = b0.w;
            br[4] = b1.x; br[5] = b1.y; br[6] = b1.z; br[7] = b1.w;
            #pragma unroll
            for (int i = 0; i < 8; i++)
                #pragma unroll
                for (int j = 0; j < 8; j++)
                    acc[i][j] += ar[i] * br[j];
        }
        __syncthreads();
    }

    // epilogue
    const int colb = bn * 128 + tx * 8;
    float badd[8];
    if (bias) {
        float4 bb0 = *(const float4*)(bias + colb);
        float4 bb1 = *(const float4*)(bias + colb + 4);
        badd[0]=bb0.x; badd[1]=bb0.y; badd[2]=bb0.z; badd[3]=bb0.w;
        badd[4]=bb1.x; badd[5]=bb1.y; badd[6]=bb1.z; badd[7]=bb1.w;
    } else {
        #pragma unroll
        for (int j = 0; j < 8; j++) badd[j] = 0.f;
    }

    #pragma unroll
    for (int i = 0; i < 8; i++) {
        const size_t row = (size_t)bm * 128 + ty * 8 + i;
        float vv[8];
        #pragma unroll
        for (int j = 0; j < 8; j++) vv[j] = acc[i][j] + badd[j];
        if (resid) {
            float4 r0 = *(const float4*)(resid + row * N + colb);
            float4 r1 = *(const float4*)(resid + row * N + colb + 4);
            vv[0]+=r0.x; vv[1]+=r0.y; vv[2]+=r0.z; vv[3]+=r0.w;
            vv[4]+=r1.x; vv[5]+=r1.y; vv[6]+=r1.z; vv[7]+=r1.w;
        }
        if (do_relu) {
            #pragma unroll
            for (int j = 0; j < 8; j++) vv[j] = fmaxf(vv[j], 0.f);
        }
        *(float4*)(Cmat + row * N + colb)     = make_float4(vv[0], vv[1], vv[2], vv[3]);
        *(float4*)(Cmat + row * N + colb + 4) = make_float4(vv[4], vv[5], vv[6], vv[7]);
    }
}

// ---------------------------------------------------------------------------
// Flash-attention (causal), fp32 SIMT.
// One block per (b, h, 64-row q tile). Q/K/V live in [B,T,C] layout
// (head h occupies columns h*64..h*64+63), so no transpose kernels needed.
// 256 threads as a 16x16 grid; each thread owns a 4x4 micro-tile.
// smem: Qs[64][64], KPs[64][65] (K tile, reused for P), Vs[64][64] = 49408 B.
// NOTE: KPs row stride is 65 floats (odd) -> NO float4 access into KPs.
//       K tile is loaded from gmem as float4 but stored as 4 scalar STS.
// ---------------------------------------------------------------------------
__global__ __launch_bounds__(256) void attn_kernel(
    const float* __restrict__ Q, const float* __restrict__ K,
    const float* __restrict__ V, float* __restrict__ O)
{
    extern __shared__ float sm[];
    float* Qs  = sm;            // 64*64
    float* KPs = sm + 4096;     // 64*65
    float* Vs  = KPs + 4160;    // 64*64

    const int tid = threadIdx.x;
    const int tx = tid & 15, ty = tid >> 4;
    const int qb = blockIdx.x, h = blockIdx.y, b = blockIdx.z;

    const size_t base = (size_t)b * TT * CC + (size_t)h * HDD;
    const float* Qb = Q + base;
    const float* Kb = K + base;
    const float* Vb = V + base;

    // load Q tile [64 rows x 64 dims]
    for (int s = tid; s < 64 * 16; s += 256) {
        int r = s >> 4, c4 = (s & 15) << 2;
        *(float4*)(Qs + r * 64 + c4) =
            *(const float4*)(Qb + (size_t)(qb * 64 + r) * CC + c4);
    }

    float m_i[4], l_i[4], oacc[4][4];
    #pragma unroll
    for (int i = 0; i < 4; i++) {
        m_i[i] = -1e30f; l_i[i] = 0.f;
        #pragma unroll
        for (int j = 0; j < 4; j++) oacc[i][j] = 0.f;
    }

    for (int kb = 0; kb <= qb; kb++) {
        __syncthreads();    // protect KPs/Vs from previous iteration's readers
        for (int s = tid; s < 64 * 16; s += 256) {
            int r = s >> 4, c4 = (s & 15) << 2;
            float4 kv4 = *(const float4*)(Kb + (size_t)(kb * 64 + r) * CC + c4);
            float* kp = KPs + r * 65 + c4;     // odd stride: scalar stores only
            kp[0] = kv4.x; kp[1] = kv4.y; kp[2] = kv4.z; kp[3] = kv4.w;
            *(float4*)(Vs + r * 64 + c4) =
                *(const float4*)(Vb + (size_t)(kb * 64 + r) * CC + c4);
        }
        __syncthreads();

        // S = Q K^T (4x4 per thread)
        float sv[4][4];
        #pragma unroll
        for (int i = 0; i < 4; i++)
            #pragma unroll
            for (int j = 0; j < 4; j++) sv[i][j] = 0.f;

        for (int d = 0; d < 64; d++) {
            float qr[4], kr[4];
            #pragma unroll
            for (int i = 0; i < 4; i++) qr[i] = Qs[(ty * 4 + i) * 64 + d];
            #pragma unroll
            for (int j = 0; j < 4; j++) kr[j] = KPs[(tx * 4 + j) * 65 + d];
            #pragma unroll
            for (int i = 0; i < 4; i++)
                #pragma unroll
                for (int j = 0; j < 4; j++) sv[i][j] += qr[i] * kr[j];
        }

        // scale + causal mask (only the diagonal block needs masking)
        const float scale = 0.125f;   // 1/sqrt(64)
        const int qrow0 = qb * 64 + ty * 4;
        const int kcol0 = kb * 64 + tx * 4;
        const bool diag = (kb == qb);
        #pragma unroll
        for (int i = 0; i < 4; i++)
            #pragma unroll
            for (int j = 0; j < 4; j++) {
                float val = sv[i][j] * scale;
                if (diag && (kcol0 + j > qrow0 + i)) val = -1e30f;
                sv[i][j] = val;
            }

        // online softmax update (rows live across half-warp: shfl width 16)
        #pragma unroll
        for (int i = 0; i < 4; i++) {
            float rm = fmaxf(fmaxf(sv[i][0], sv[i][1]), fmaxf(sv[i][2], sv[i][3]));
            #pragma unroll
            for (int msk = 1; msk < 16; msk <<= 1)
                rm = fmaxf(rm, __shfl_xor_sync(0xffffffffu, rm, msk));
            const float mnew = fmaxf(m_i[i], rm);
            const float alpha = __expf(m_i[i] - mnew);
            l_i[i] *= alpha;
            #pragma unroll
            for (int j = 0; j < 4; j++) oacc[i][j] *= alpha;
            float rs = 0.f;
            #pragma unroll
            for (int j = 0; j < 4; j++) {
                sv[i][j] = __expf(sv[i][j] - mnew);
                rs += sv[i][j];
            }
            #pragma unroll
            for (int msk = 1; msk < 16; msk <<= 1)
                rs += __shfl_xor_sync(0xffffffffu, rs, msk);
            l_i[i] += rs;
            m_i[i] = mnew;
        }

        __syncthreads();   // all reads of K tile complete
        // write P into the K tile region (scalar — odd stride)
        #pragma unroll
        for (int i = 0; i < 4; i++)
            #pragma unroll
            for (int j = 0; j < 4; j++)
                KPs[(ty * 4 + i) * 65 + tx * 4 + j] = sv[i][j];
        __syncthreads();

        // O += P V
        for (int d = 0; d < 64; d++) {
            float pr[4], vr[4];
            #pragma unroll
            for (int i = 0; i < 4; i++) pr[i] = KPs[(ty * 4 + i) * 65 + d];
            #pragma unroll
            for (int j = 0; j < 4; j++) vr[j] = Vs[d * 64 + tx * 4 + j];
            #pragma unroll
            for (int i = 0; i < 4; i++)
                #pragma unroll
                for (int j = 0; j < 4; j++) oacc[i][j] += pr[i] * vr[j];
        }
    }

    // write O (normalized) back into [B,T,C] layout
    float* Ob = O + base;
    #pragma unroll
    for (int i = 0; i < 4; i++) {
        const float inv = 1.0f / l_i[i];
        float4 ov = make_float4(oacc[i][0] * inv, oacc[i][1] * inv,
                                oacc[i][2] * inv, oacc[i][3] * inv);
        *(float4*)(Ob + (size_t)(qb * 64 + ty * 4 + i) * CC + tx * 4) = ov;
    }
}

// ---------------------------------------------------------------------------
// Launch
// ---------------------------------------------------------------------------
extern "C" void kernel_launch(void* const* d_in, const int* in_sizes, int n_in,
                              void* d_out, int out_size)
{
    const float* x     = (const float*)d_in[0];
    const float* ln1_w = (const float*)d_in[1];
    const float* ln1_b = (const float*)d_in[2];
    const float* Wq    = (const float*)d_in[3];
    const float* Wk    = (const float*)d_in[4];
    const float* Wv    = (const float*)d_in[5];
    const float* Wp    = (const float*)d_in[6];
    const float* bp    = (const float*)d_in[7];
    const float* ln2_w = (const float*)d_in[8];
    const float* ln2_b = (const float*)d_in[9];
    const float* W1    = (const float*)d_in[10];
    const float* b1    = (const float*)d_in[11];
    const float* W2    = (const float*)d_in[12];
    const float* b2    = (const float*)d_in[13];

    float *h, *q, *k, *v, *o, *x1, *h2, *ff;
    cudaGetSymbolAddress((void**)&h,  g_h);
    cudaGetSymbolAddress((void**)&q,  g_q);
    cudaGetSymbolAddress((void**)&k,  g_k);
    cudaGetSymbolAddress((void**)&v,  g_v);
    cudaGetSymbolAddress((void**)&o,  g_o);
    cudaGetSymbolAddress((void**)&x1, g_x1);
    cudaGetSymbolAddress((void**)&h2, g_h2);
    cudaGetSymbolAddress((void**)&ff, g_ff);

    // 1. h = LN1(x)
    ln_kernel<<<MM, 256>>>(x, ln1_w, ln1_b, h);

    // 2. q/k/v = h @ W{q,k,v}   (kept in [B,T,C] layout)
    dim3 gQKV(CC / 128, MM / 128);
    sgemm_kernel<<<gQKV, 256>>>(h, Wq, nullptr, nullptr, q, MM, CC, CC, 0);
    sgemm_kernel<<<gQKV, 256>>>(h, Wk, nullptr, nullptr, k, MM, CC, CC, 0);
    sgemm_kernel<<<gQKV, 256>>>(h, Wv, nullptr, nullptr, v, MM, CC, CC, 0);

    // 3. o = causal_attention(q, k, v)
    const size_t attn_smem = (4096 + 4160 + 4096) * sizeof(float);  // 49408
    cudaFuncSetAttribute(attn_kernel,
                         cudaFuncAttributeMaxDynamicSharedMemorySize,
                         (int)attn_smem);
    dim3 gA(TT / 64, NHH, BB);
    attn_kernel<<<gA, 256, attn_smem>>>(q, k, v, o);

    // 4. x1 = x + o @ Wp + bp
    sgemm_kernel<<<gQKV, 256>>>(o, Wp, bp, x, x1, MM, CC, CC, 0);

    // 5. h2 = LN2(x1)
    ln_kernel<<<MM, 256>>>(x1, ln2_w, ln2_b, h2);

    // 6. ff = relu(h2 @ W1 + b1)
    dim3 gFF(FFF / 128, MM / 128);
    sgemm_kernel<<<gFF, 256>>>(h2, W1, b1, nullptr, ff, MM, FFF, CC, 1);

    // 7. out = x1 + ff @ W2 + b2
    dim3 gOut(CC / 128, MM / 128);
    sgemm_kernel<<<gOut, 256>>>(ff, W2, b2, x1, (float*)d_out, MM, CC, FFF, 0);
}

// round 6
// speedup vs baseline: 1.1743x; 1.1743x over previous
#include <cuda_runtime.h>
#include <cuda_bf16.h>
#include <cstddef>

// Problem constants
#define BB 2
#define TT 2048
#define CC 1024
#define NHH 16
#define HDD 64
#define FFF 4096
#define MM (BB*TT)   // 4096

// ---------------------------------------------------------------------------
// Scratch (static device arrays — allocation-free per harness rules)
// ---------------------------------------------------------------------------
__device__ float g_h [MM*CC];   // LN1 output
__device__ float g_q [MM*CC];
__device__ float g_k [MM*CC];
__device__ float g_v [MM*CC];
__device__ float g_o [MM*CC];   // attention output, [B,T,C] layout
__device__ float g_x1[MM*CC];   // x + attn proj (residual 1)
__device__ float g_h2[MM*CC];   // LN2 output
__device__ float g_ff[MM*FFF];  // relu(h2@W1+b1)

// ---------------------------------------------------------------------------
// Packed fp32x2 helpers (sm_100+ PTX; ptxas never auto-fuses these).
// FFMA2 doubles FLOP/issue vs 3-reg FFMA (rt_SMSP=2 either way).
// ---------------------------------------------------------------------------
__device__ __forceinline__ void ffma2(unsigned long long& d,
                                      unsigned long long a,
                                      unsigned long long b) {
    asm("fma.rn.f32x2 %0, %1, %2, %0;" : "+l"(d) : "l"(a), "l"(b));
}
__device__ __forceinline__ unsigned long long dup2(float x) {
    unsigned long long r;
    asm("mov.b64 %0, {%1, %1};" : "=l"(r) : "f"(x));
    return r;
}
__device__ __forceinline__ unsigned long long pack2(float lo, float hi) {
    unsigned long long r;
    asm("mov.b64 %0, {%1, %2};" : "=l"(r) : "f"(lo), "f"(hi));
    return r;
}
__device__ __forceinline__ float2 unpk2(unsigned long long v) {
    float2 f;
    asm("mov.b64 {%0, %1}, %2;" : "=f"(f.x), "=f"(f.y) : "l"(v));
    return f;
}

// ---------------------------------------------------------------------------
// LayerNorm: one block per row, 256 threads, C=1024 (4 floats / thread)
// ---------------------------------------------------------------------------
__global__ __launch_bounds__(256) void ln_kernel(
    const float* __restrict__ x, const float* __restrict__ w,
    const float* __restrict__ bb, float* __restrict__ out)
{
    const int row = blockIdx.x;
    const int tid = threadIdx.x;
    const float* xr = x + (size_t)row * CC;
    float4 xv = ((const float4*)xr)[tid];

    float s  = xv.x + xv.y + xv.z + xv.w;
    float sq = xv.x*xv.x + xv.y*xv.y + xv.z*xv.z + xv.w*xv.w;

    #pragma unroll
    for (int m = 16; m > 0; m >>= 1) {
        s  += __shfl_xor_sync(0xffffffffu, s,  m);
        sq += __shfl_xor_sync(0xffffffffu, sq, m);
    }
    __shared__ float ss[8], ssq[8];
    const int lane = tid & 31, wid = tid >> 5;
    if (lane == 0) { ss[wid] = s; ssq[wid] = sq; }
    __syncthreads();
    float ts = 0.f, tsq = 0.f;
    #pragma unroll
    for (int i = 0; i < 8; i++) { ts += ss[i]; tsq += ssq[i]; }

    const float mu  = ts * (1.0f / CC);
    const float var = tsq * (1.0f / CC) - mu * mu;
    const float rs  = rsqrtf(var + 1e-5f);

    float4 wv = ((const float4*)w)[tid];
    float4 bv = ((const float4*)bb)[tid];
    float4 ov;
    ov.x = (xv.x - mu) * rs * wv.x + bv.x;
    ov.y = (xv.y - mu) * rs * wv.y + bv.y;
    ov.z = (xv.z - mu) * rs * wv.z + bv.z;
    ov.w = (xv.w - mu) * rs * wv.w + bv.w;
    ((float4*)(out + (size_t)row * CC))[tid] = ov;
}

// ---------------------------------------------------------------------------
// SGEMM: C[M,N] = A[M,K] @ B[K,N] (+bias[N]) (+resid[M,N]) (relu?)
// 128x128 block tile, BK=16, 8x8 per thread (as 8x4 f32x2 pairs), 256 threads.
// Double-buffered smem, global prefetch into registers, FFMA2 inner loop.
// M,N multiples of 128; K multiple of 16 (true for all 6 GEMMs here).
// ---------------------------------------------------------------------------
__global__ __launch_bounds__(256) void sgemm_kernel(
    const float* __restrict__ A, const float* __restrict__ B,
    const float* __restrict__ bias, const float* __restrict__ resid,
    float* __restrict__ Cmat, int M, int N, int K, int do_relu)
{
    __shared__ float As[2][16][132];   // transposed, padded (store 2-way, read bcast)
    __shared__ float Bs[2][16][128];

    const int tid = threadIdx.x;
    const int tx = tid & 15;        // 16 col-groups of 8
    const int ty = tid >> 4;        // 16 row-groups of 8
    const int bm = blockIdx.y, bn = blockIdx.x;

    const float* Ab = A + (size_t)bm * 128 * K;
    const float* Bb = B + (size_t)bn * 128;

    // per-thread load coordinates (2 float4 each for A and B per tile)
    const int a_r0 = tid >> 2,            a_c0 = (tid & 3) << 2;
    const int b_r0 = tid >> 5,            b_c0 = (tid & 31) << 2;
    const int a_r1 = (tid + 256) >> 2,    a_c1 = a_c0;          // (tid+256)&3 == tid&3
    const int b_r1 = ((tid + 256) >> 5),  b_c1 = b_c0;

    unsigned long long acc2[8][4];
    #pragma unroll
    for (int i = 0; i < 8; i++)
        #pragma unroll
        for (int j = 0; j < 4; j++) acc2[i][j] = 0ull;

    float4 a_st0, a_st1, b_st0, b_st1;

    // prologue: load tile 0
    {
        a_st0 = *(const float4*)(Ab + (size_t)a_r0 * K + a_c0);
        a_st1 = *(const float4*)(Ab + (size_t)a_r1 * K + a_c1);
        b_st0 = *(const float4*)(Bb + (size_t)b_r0 * N + b_c0);
        b_st1 = *(const float4*)(Bb + (size_t)b_r1 * N + b_c1);
        As[0][a_c0+0][a_r0]=a_st0.x; As[0][a_c0+1][a_r0]=a_st0.y;
        As[0][a_c0+2][a_r0]=a_st0.z; As[0][a_c0+3][a_r0]=a_st0.w;
        As[0][a_c1+0][a_r1]=a_st1.x; As[0][a_c1+1][a_r1]=a_st1.y;
        As[0][a_c1+2][a_r1]=a_st1.z; As[0][a_c1+3][a_r1]=a_st1.w;
        *(float4*)(&Bs[0][b_r0][b_c0]) = b_st0;
        *(float4*)(&Bs[0][b_r1][b_c1]) = b_st1;
    }
    __syncthreads();

    const int nt = K >> 4;
    int cur = 0;
    for (int t = 0; t < nt; t++) {
        // prefetch next tile into registers (overlaps with compute below)
        if (t + 1 < nt) {
            const int k0 = (t + 1) << 4;
            a_st0 = *(const float4*)(Ab + (size_t)a_r0 * K + k0 + a_c0);
            a_st1 = *(const float4*)(Ab + (size_t)a_r1 * K + k0 + a_c1);
            b_st0 = *(const float4*)(Bb + (size_t)(k0 + b_r0) * N + b_c0);
            b_st1 = *(const float4*)(Bb + (size_t)(k0 + b_r1) * N + b_c1);
        }

        #pragma unroll
        for (int kk = 0; kk < 16; kk++) {
            float4 a0 = *(float4*)(&As[cur][kk][ty * 8]);
            float4 a1 = *(float4*)(&As[cur][kk][ty * 8 + 4]);
            float4 b0 = *(float4*)(&Bs[cur][kk][tx * 8]);
            float4 b1 = *(float4*)(&Bs[cur][kk][tx * 8 + 4]);
            unsigned long long bp[4];
            bp[0] = pack2(b0.x, b0.y); bp[1] = pack2(b0.z, b0.w);
            bp[2] = pack2(b1.x, b1.y); bp[3] = pack2(b1.z, b1.w);
            float av[8] = {a0.x, a0.y, a0.z, a0.w, a1.x, a1.y, a1.z, a1.w};
            #pragma unroll
            for (int i = 0; i < 8; i++) {
                const unsigned long long ad = dup2(av[i]);
                ffma2(acc2[i][0], ad, bp[0]);
                ffma2(acc2[i][1], ad, bp[1]);
                ffma2(acc2[i][2], ad, bp[2]);
                ffma2(acc2[i][3], ad, bp[3]);
            }
        }

        if (t + 1 < nt) {
            const int nxt = cur ^ 1;
            As[nxt][a_c0+0][a_r0]=a_st0.x; As[nxt][a_c0+1][a_r0]=a_st0.y;
            As[nxt][a_c0+2][a_r0]=a_st0.z; As[nxt][a_c0+3][a_r0]=a_st0.w;
            As[nxt][a_c1+0][a_r1]=a_st1.x; As[nxt][a_c1+1][a_r1]=a_st1.y;
            As[nxt][a_c1+2][a_r1]=a_st1.z; As[nxt][a_c1+3][a_r1]=a_st1.w;
            *(float4*)(&Bs[nxt][b_r0][b_c0]) = b_st0;
            *(float4*)(&Bs[nxt][b_r1][b_c1]) = b_st1;
            __syncthreads();
            cur = nxt;
        }
    }

    // epilogue
    const int colb = bn * 128 + tx * 8;
    float badd[8];
    if (bias) {
        float4 bb0 = *(const float4*)(bias + colb);
        float4 bb1 = *(const float4*)(bias + colb + 4);
        badd[0]=bb0.x; badd[1]=bb0.y; badd[2]=bb0.z; badd[3]=bb0.w;
        badd[4]=bb1.x; badd[5]=bb1.y; badd[6]=bb1.z; badd[7]=bb1.w;
    } else {
        #pragma unroll
        for (int j = 0; j < 8; j++) badd[j] = 0.f;
    }

    #pragma unroll
    for (int i = 0; i < 8; i++) {
        const size_t row = (size_t)bm * 128 + ty * 8 + i;
        float vv[8];
        float2 p0 = unpk2(acc2[i][0]), p1 = unpk2(acc2[i][1]);
        float2 p2 = unpk2(acc2[i][2]), p3 = unpk2(acc2[i][3]);
        vv[0]=p0.x+badd[0]; vv[1]=p0.y+badd[1]; vv[2]=p1.x+badd[2]; vv[3]=p1.y+badd[3];
        vv[4]=p2.x+badd[4]; vv[5]=p2.y+badd[5]; vv[6]=p3.x+badd[6]; vv[7]=p3.y+badd[7];
        if (resid) {
            float4 r0 = *(const float4*)(resid + row * N + colb);
            float4 r1 = *(const float4*)(resid + row * N + colb + 4);
            vv[0]+=r0.x; vv[1]+=r0.y; vv[2]+=r0.z; vv[3]+=r0.w;
            vv[4]+=r1.x; vv[5]+=r1.y; vv[6]+=r1.z; vv[7]+=r1.w;
        }
        if (do_relu) {
            #pragma unroll
            for (int j = 0; j < 8; j++) vv[j] = fmaxf(vv[j], 0.f);
        }
        *(float4*)(Cmat + row * N + colb)     = make_float4(vv[0], vv[1], vv[2], vv[3]);
        *(float4*)(Cmat + row * N + colb + 4) = make_float4(vv[4], vv[5], vv[6], vv[7]);
    }
}

// ---------------------------------------------------------------------------
// Flash-attention (causal), fp32 SIMT.
// One block per (b, h, 64-row q tile). Q/K/V live in [B,T,C] layout
// (head h occupies columns h*64..h*64+63), so no transpose kernels needed.
// 256 threads as a 16x16 grid; each thread owns a 4x4 micro-tile.
// smem: Qs[64][64], KPs[64][65] (K tile, reused for P), Vs[64][64] = 49408 B.
// NOTE: KPs row stride is 65 floats (odd) -> NO float4 access into KPs.
// ---------------------------------------------------------------------------
__global__ __launch_bounds__(256) void attn_kernel(
    const float* __restrict__ Q, const float* __restrict__ K,
    const float* __restrict__ V, float* __restrict__ O)
{
    extern __shared__ float sm[];
    float* Qs  = sm;            // 64*64
    float* KPs = sm + 4096;     // 64*65
    float* Vs  = KPs + 4160;    // 64*64

    const int tid = threadIdx.x;
    const int tx = tid & 15, ty = tid >> 4;
    const int qb = blockIdx.x, h = blockIdx.y, b = blockIdx.z;

    const size_t base = (size_t)b * TT * CC + (size_t)h * HDD;
    const float* Qb = Q + base;
    const float* Kb = K + base;
    const float* Vb = V + base;

    // load Q tile [64 rows x 64 dims]
    for (int s = tid; s < 64 * 16; s += 256) {
        int r = s >> 4, c4 = (s & 15) << 2;
        *(float4*)(Qs + r * 64 + c4) =
            *(const float4*)(Qb + (size_t)(qb * 64 + r) * CC + c4);
    }

    float m_i[4], l_i[4], oacc[4][4];
    #pragma unroll
    for (int i = 0; i < 4; i++) {
        m_i[i] = -1e30f; l_i[i] = 0.f;
        #pragma unroll
        for (int j = 0; j < 4; j++) oacc[i][j] = 0.f;
    }

    for (int kb = 0; kb <= qb; kb++) {
        __syncthreads();    // protect KPs/Vs from previous iteration's readers
        for (int s = tid; s < 64 * 16; s += 256) {
            int r = s >> 4, c4 = (s & 15) << 2;
            float4 kv4 = *(const float4*)(Kb + (size_t)(kb * 64 + r) * CC + c4);
            float* kp = KPs + r * 65 + c4;     // odd stride: scalar stores only
            kp[0] = kv4.x; kp[1] = kv4.y; kp[2] = kv4.z; kp[3] = kv4.w;
            *(float4*)(Vs + r * 64 + c4) =
                *(const float4*)(Vb + (size_t)(kb * 64 + r) * CC + c4);
        }
        __syncthreads();

        // S = Q K^T (4x4 per thread)
        float sv[4][4];
        #pragma unroll
        for (int i = 0; i < 4; i++)
            #pragma unroll
            for (int j = 0; j < 4; j++) sv[i][j] = 0.f;

        for (int d = 0; d < 64; d++) {
            float qr[4], kr[4];
            #pragma unroll
            for (int i = 0; i < 4; i++) qr[i] = Qs[(ty * 4 + i) * 64 + d];
            #pragma unroll
            for (int j = 0; j < 4; j++) kr[j] = KPs[(tx * 4 + j) * 65 + d];
            #pragma unroll
            for (int i = 0; i < 4; i++)
                #pragma unroll
                for (int j = 0; j < 4; j++) sv[i][j] += qr[i] * kr[j];
        }

        // scale + causal mask (only the diagonal block needs masking)
        const float scale = 0.125f;   // 1/sqrt(64)
        const int qrow0 = qb * 64 + ty * 4;
        const int kcol0 = kb * 64 + tx * 4;
        const bool diag = (kb == qb);
        #pragma unroll
        for (int i = 0; i < 4; i++)
            #pragma unroll
            for (int j = 0; j < 4; j++) {
                float val = sv[i][j] * scale;
                if (diag && (kcol0 + j > qrow0 + i)) val = -1e30f;
                sv[i][j] = val;
            }

        // online softmax update (rows live across half-warp: shfl width 16)
        #pragma unroll
        for (int i = 0; i < 4; i++) {
            float rm = fmaxf(fmaxf(sv[i][0], sv[i][1]), fmaxf(sv[i][2], sv[i][3]));
            #pragma unroll
            for (int msk = 1; msk < 16; msk <<= 1)
                rm = fmaxf(rm, __shfl_xor_sync(0xffffffffu, rm, msk));
            const float mnew = fmaxf(m_i[i], rm);
            const float alpha = __expf(m_i[i] - mnew);
            l_i[i] *= alpha;
            #pragma unroll
            for (int j = 0; j < 4; j++) oacc[i][j] *= alpha;
            float rs = 0.f;
            #pragma unroll
            for (int j = 0; j < 4; j++) {
                sv[i][j] = __expf(sv[i][j] - mnew);
                rs += sv[i][j];
            }
            #pragma unroll
            for (int msk = 1; msk < 16; msk <<= 1)
                rs += __shfl_xor_sync(0xffffffffu, rs, msk);
            l_i[i] += rs;
            m_i[i] = mnew;
        }

        __syncthreads();   // all reads of K tile complete
        // write P into the K tile region (scalar — odd stride)
        #pragma unroll
        for (int i = 0; i < 4; i++)
            #pragma unroll
            for (int j = 0; j < 4; j++)
                KPs[(ty * 4 + i) * 65 + tx * 4 + j] = sv[i][j];
        __syncthreads();

        // O += P V
        for (int d = 0; d < 64; d++) {
            float pr[4], vr[4];
            #pragma unroll
            for (int i = 0; i < 4; i++) pr[i] = KPs[(ty * 4 + i) * 65 + d];
            #pragma unroll
            for (int j = 0; j < 4; j++) vr[j] = Vs[d * 64 + tx * 4 + j];
            #pragma unroll
            for (int i = 0; i < 4; i++)
                #pragma unroll
                for (int j = 0; j < 4; j++) oacc[i][j] += pr[i] * vr[j];
        }
    }

    // write O (normalized) back into [B,T,C] layout
    float* Ob = O + base;
    #pragma unroll
    for (int i = 0; i < 4; i++) {
        const float inv = 1.0f / l_i[i];
        float4 ov = make_float4(oacc[i][0] * inv, oacc[i][1] * inv,
                                oacc[i][2] * inv, oacc[i][3] * inv);
        *(float4*)(Ob + (size_t)(qb * 64 + ty * 4 + i) * CC + tx * 4) = ov;
    }
}

// ---------------------------------------------------------------------------
// Launch
// ---------------------------------------------------------------------------
extern "C" void kernel_launch(void* const* d_in, const int* in_sizes, int n_in,
                              void* d_out, int out_size)
{
    const float* x     = (const float*)d_in[0];
    const float* ln1_w = (const float*)d_in[1];
    const float* ln1_b = (const float*)d_in[2];
    const float* Wq    = (const float*)d_in[3];
    const float* Wk    = (const float*)d_in[4];
    const float* Wv    = (const float*)d_in[5];
    const float* Wp    = (const float*)d_in[6];
    const float* bp    = (const float*)d_in[7];
    const float* ln2_w = (const float*)d_in[8];
    const float* ln2_b = (const float*)d_in[9];
    const float* W1    = (const float*)d_in[10];
    const float* b1    = (const float*)d_in[11];
    const float* W2    = (const float*)d_in[12];
    const float* b2    = (const float*)d_in[13];

    float *h, *q, *k, *v, *o, *x1, *h2, *ff;
    cudaGetSymbolAddress((void**)&h,  g_h);
    cudaGetSymbolAddress((void**)&q,  g_q);
    cudaGetSymbolAddress((void**)&k,  g_k);
    cudaGetSymbolAddress((void**)&v,  g_v);
    cudaGetSymbolAddress((void**)&o,  g_o);
    cudaGetSymbolAddress((void**)&x1, g_x1);
    cudaGetSymbolAddress((void**)&h2, g_h2);
    cudaGetSymbolAddress((void**)&ff, g_ff);

    // 1. h = LN1(x)
    ln_kernel<<<MM, 256>>>(x, ln1_w, ln1_b, h);

    // 2. q/k/v = h @ W{q,k,v}   (kept in [B,T,C] layout)
    dim3 gQKV(CC / 128, MM / 128);
    sgemm_kernel<<<gQKV, 256>>>(h, Wq, nullptr, nullptr, q, MM, CC, CC, 0);
    sgemm_kernel<<<gQKV, 256>>>(h, Wk, nullptr, nullptr, k, MM, CC, CC, 0);
    sgemm_kernel<<<gQKV, 256>>>(h, Wv, nullptr, nullptr, v, MM, CC, CC, 0);

    // 3. o = causal_attention(q, k, v)
    const size_t attn_smem = (4096 + 4160 + 4096) * sizeof(float);  // 49408
    cudaFuncSetAttribute(attn_kernel,
                         cudaFuncAttributeMaxDynamicSharedMemorySize,
                         (int)attn_smem);
    dim3 gA(TT / 64, NHH, BB);
    attn_kernel<<<gA, 256, attn_smem>>>(q, k, v, o);

    // 4. x1 = x + o @ Wp + bp
    sgemm_kernel<<<gQKV, 256>>>(o, Wp, bp, x, x1, MM, CC, CC, 0);

    // 5. h2 = LN2(x1)
    ln_kernel<<<MM, 256>>>(x1, ln2_w, ln2_b, h2);

    // 6. ff = relu(h2 @ W1 + b1)
    dim3 gFF(FFF / 128, MM / 128);
    sgemm_kernel<<<gFF, 256>>>(h2, W1, b1, nullptr, ff, MM, FFF, CC, 1);

    // 7. out = x1 + ff @ W2 + b2
    dim3 gOut(CC / 128, MM / 128);
    sgemm_kernel<<<gOut, 256>>>(ff, W2, b2, x1, (float*)d_out, MM, CC, FFF, 0);
}